// round 12
// baseline (speedup 1.0000x reference)
#include <cuda_runtime.h>
#include <math.h>

#define Bb 64
#define Cc 8
#define Nn 2048
#define Tt 64
#define NSPLIT 4
#define NROWS (Nn / NSPLIT)                 // 512 rows per reduce block
#define RED_BLOCKS (Bb * Cc * NSPLIT)       // 2048 (32 per batch, batch-major)
#define AGG_BLOCKS (Bb * 128)               // 8192 (batch-major)
#define NT4 (Nn * Tt / 4)                   // 32768 float4 per (b,c)

// scratch
__device__ float g_part[Bb * Cc * NSPLIT * Tt];   // 512 KB
__device__ float g_att[Bb * Cc * Cc];
__device__ int   g_cnt[Bb];                       // reduce completion counters
__device__ int   g_ready[Bb];                     // att ready flags
__device__ int   g_done[Bb];                      // agg completion counters

union SmemU {
    struct { float alpha[NROWS]; float4 red[256]; } r;            // 6 KB
    struct { float W[64 * 64]; float k[8 * 64]; float m[8 * 64];
             float sc[64]; } t;                                   // ~20.5 KB
};

// ---------------------------------------------------------------------------
// Kernel 1: partial k + last-block-per-batch att[b] + ready flag.
// Batch-major block order: bid>>5 = b. PLAIN loads: leave x tail in L2.
// ---------------------------------------------------------------------------
__global__ void __launch_bounds__(256)
k_reduce_att(const float* __restrict__ x, const float* __restrict__ alpha,
             const float* __restrict__ Wc) {
#if __CUDA_ARCH__ >= 900
    cudaTriggerProgrammaticLaunchCompletion();   // let agg dispatch once all
#endif                                           // reduce CTAs have launched
    __shared__ SmemU S;
    __shared__ int s_last;

    int b     = blockIdx.x >> 5;
    int sub   = blockIdx.x & 31;
    int c     = sub >> 2;
    int split = sub & 3;
    int bc    = b * Cc + c;
    const float* xp = x + (long)bc * Nn * Tt + (long)split * NROWS * Tt;

    int tid = threadIdx.x;
    for (int i = tid; i < NROWS; i += 256) S.r.alpha[i] = alpha[split * NROWS + i];
    __syncthreads();

    int t4 = tid & 15, row = tid >> 4;
    float4 acc = make_float4(0.f, 0.f, 0.f, 0.f);
    const float4* xv = reinterpret_cast<const float4*>(xp) + t4;

    #pragma unroll 8
    for (int i = 0; i < NROWS / 16; i++) {   // 32 iters; PLAIN ld -> stays in L2
        int nl = row + i * 16;
        float4 v = xv[(long)nl * 16];
        float a = S.r.alpha[nl];
        acc.x += v.x * a; acc.y += v.y * a;
        acc.z += v.z * a; acc.w += v.w * a;
    }

    S.r.red[tid] = acc;
    __syncthreads();
    #pragma unroll
    for (int off = 8; off >= 1; off >>= 1) {
        if (row < off) {
            float4 o = S.r.red[(row + off) * 16 + t4];
            acc.x += o.x; acc.y += o.y; acc.z += o.z; acc.w += o.w;
            S.r.red[tid] = acc;
        }
        __syncthreads();
    }
    if (row == 0)
        reinterpret_cast<float4*>(
            g_part + ((long)bc * NSPLIT + split) * Tt)[t4] = acc;

    // ---- last-block-per-batch tail: att[b] ----
    __threadfence();
    if (tid == 0)
        s_last = (atomicAdd(&g_cnt[b], 1) == 32 - 1);
    __syncthreads();
    if (!s_last) return;

    for (int i = tid; i < 64 * 64; i += 256) S.t.W[i] = Wc[i];
    for (int i = tid; i < 8 * 64; i += 256) {
        int cc = i >> 6, t = i & 63;
        const float* gp = g_part + ((long)(b * Cc + cc) * NSPLIT) * Tt + t;
        float s = 0.f;
        #pragma unroll
        for (int p = 0; p < NSPLIT; p++) s += gp[p * Tt];
        S.t.k[i] = s;
    }
    __syncthreads();

    for (int e = tid; e < 512; e += 256) {
        int cc = e >> 6, s = e & 63;
        float a2 = 0.f;
        #pragma unroll
        for (int t = 0; t < 64; t++) a2 += S.t.k[cc * 64 + t] * S.t.W[t * 64 + s];
        S.t.m[e] = a2;
    }
    __syncthreads();

    if (tid < 64) {
        int cc = tid >> 3, d = tid & 7;
        float sc = 0.f;
        #pragma unroll
        for (int s = 0; s < 64; s++) sc += S.t.m[cc * 64 + s] * S.t.k[d * 64 + s];
        S.t.sc[tid] = sc;
    }
    __syncthreads();

    if (tid < 8) {
        float mx = -1e30f;
        #pragma unroll
        for (int j = 0; j < 8; j++) mx = fmaxf(mx, S.t.sc[tid * 8 + j]);
        float e[8], sum = 0.f;
        #pragma unroll
        for (int j = 0; j < 8; j++) { e[j] = __expf(S.t.sc[tid * 8 + j] - mx); sum += e[j]; }
        float inv = 1.f / sum;
        #pragma unroll
        for (int j = 0; j < 8; j++)
            g_att[b * Cc * Cc + tid * Cc + j] = e[j] * inv;
    }
    __syncthreads();
    if (tid == 0) {
        g_cnt[b] = 0;                        // reset for next replay
        __threadfence();
        atomicExch(&g_ready[b], 1);          // release att[b]
    }
}

// ---------------------------------------------------------------------------
// Kernel 2: aggregation (PDL secondary). Forward batch order = ready order.
// Spins on g_ready[b]; last block per batch resets flags for next replay.
// ---------------------------------------------------------------------------
__global__ void __launch_bounds__(256)
k_agg(const float* __restrict__ x, float* __restrict__ out) {
    int b     = blockIdx.x >> 7;                 // forward order
    int chunk = blockIdx.x & 127;
    int tid   = threadIdx.x;

    if (tid == 0) {
        while (atomicAdd(&g_ready[b], 0) == 0) __nanosleep(128);
    }
    __syncthreads();
    __threadfence();                             // acquire att[b]

    __shared__ float satt[64];
    if (tid < 64) satt[tid] = g_att[b * 64 + tid];
    __syncthreads();

    int p = chunk * 256 + tid;
    const float4* xb = reinterpret_cast<const float4*>(x + (long)b * Cc * Nn * Tt) + p;
    float4*       ob = reinterpret_cast<float4*>(out + (long)b * Cc * Nn * Tt) + p;

    float4 v[8];
    #pragma unroll
    for (int i = 0; i < 8; i++)
        v[i] = __ldcs(xb + (long)i * NT4);       // evict-first: x dead after this

    #pragma unroll
    for (int c = 0; c < 8; c++) {
        float a0 = satt[c * 8];
        float4 acc;
        acc.x = a0 * v[0].x; acc.y = a0 * v[0].y;
        acc.z = a0 * v[0].z; acc.w = a0 * v[0].w;
        #pragma unroll
        for (int i = 1; i < 8; i++) {
            float a = satt[c * 8 + i];
            acc.x += a * v[i].x; acc.y += a * v[i].y;
            acc.z += a * v[i].z; acc.w += a * v[i].w;
        }
        __stcs(ob + (long)c * NT4, acc);
    }

    __syncthreads();
    if (tid == 0) {
        if (atomicAdd(&g_done[b], 1) == 128 - 1) {
            g_done[b] = 0;                       // reset for next replay
            atomicExch(&g_ready[b], 0);
        }
    }
}

// ---------------------------------------------------------------------------
extern "C" void kernel_launch(void* const* d_in, const int* in_sizes, int n_in,
                              void* d_out, int out_size) {
    const float* x     = (const float*)d_in[0];
    const float* Wc    = (const float*)d_in[1];
    const float* alpha = (const float*)d_in[2];
    float* out = (float*)d_out;

    k_reduce_att<<<RED_BLOCKS, 256>>>(x, alpha, Wc);   // primary

    cudaLaunchAttribute attr[1];
    attr[0].id = cudaLaunchAttributeProgrammaticStreamSerialization;
    attr[0].val.programmaticStreamSerializationAllowed = 1;

    cudaLaunchConfig_t cfg = {};
    cfg.gridDim = dim3(AGG_BLOCKS);
    cfg.blockDim = dim3(256);
    cfg.dynamicSmemBytes = 0;
    cfg.stream = 0;
    cfg.attrs = attr;
    cfg.numAttrs = 1;
    cudaLaunchKernelEx(&cfg, k_agg, x, out);           // PDL secondary
}